// round 13
// baseline (speedup 1.0000x reference)
#include <cuda_runtime.h>
#include <cuda_fp16.h>
#include <cstdint>

// ---------------- problem dims (fixed) ----------------
#define BATCH   32
#define RDIM    5
#define NNODES  1024
#define DDIM    256
#define HDIM    256
#define MTOT    (BATCH * NNODES)    // 32768

// ---------------- tiling (R9-proven GEMM core) ----------------
#define TM      128                 // CTA M tile
#define TH      64                  // CTA H tile
#define SA      264                 // padded A row stride (fp16 elems), 528 B
#define SAB     (SA * 2)
#define ASZ     (TM * SAB)          // 67584 B per A buffer

// w0 chunks: 64 rows x 128 cols fp16, row stride 272 B (hi at 0, lo at +BCHUNK)
#define BROW    272
#define BCHUNK  (TH * BROW)         // 17408
// relation chunks: 64 rows x 256 cols fp16, row stride 528 B
#define BROWR   528
#define BSTAGE  34816               // stage slot (fits both chunk types)
#define NCHUNK  7                   // c0,c1: w0 half-K (3-pass); c2..c6: rel full-K

#define SM_AHI  0
#define SM_ALO  (ASZ)
#define SM_B0   (2 * ASZ)                  // 135168
#define SM_TOTAL (SM_B0 + 2 * BSTAGE)      // 204800 B

// heterogeneous grid: groups of 9 = 5 rowsum + 4 GEMM, x 256 m-tiles
#define GROUP   9
#define NGROUPS 256
#define NBLOCKS (GROUP * NGROUPS)          // 2304

// ---------------- device scratch ----------------
__device__ __align__(16) __half g_nhi[MTOT * DDIM];        // nodes fp16 hi [m][d]
__device__ __align__(16) __half g_nlo[MTOT * DDIM];        // nodes fp16 lo
__device__ __align__(16) __half g_whi[6 * HDIM * DDIM];    // [g][h][d] fp16 (g0=w0)
__device__ __align__(16) __half g_wlo[HDIM * DDIM];        // w0 fp16 lo
__device__ float g_invc[BATCH * RDIM * NNODES];            // 1/rowsum (0 -> 1)
__device__ int   g_flag[NGROUPS];                          // rowsum-done counters

// ---------------- helpers ----------------
__device__ __forceinline__ uint32_t smem_u32(const void* p) {
    uint32_t a;
    asm("{ .reg .u64 t; cvta.to.shared.u64 t, %1; cvt.u32.u64 %0, t; }" : "=r"(a) : "l"(p));
    return a;
}
__device__ __forceinline__ void ldm4(uint32_t* r, uint32_t addr) {
    asm volatile("ldmatrix.sync.aligned.m8n8.x4.shared.b16 {%0,%1,%2,%3}, [%4];"
                 : "=r"(r[0]), "=r"(r[1]), "=r"(r[2]), "=r"(r[3]) : "r"(addr));
}
__device__ __forceinline__ void mma16816(float* c, const uint32_t* a,
                                         uint32_t b0, uint32_t b1) {
    asm volatile("mma.sync.aligned.m16n8k16.row.col.f32.f16.f16.f32 "
                 "{%0,%1,%2,%3}, {%4,%5,%6,%7}, {%8,%9}, {%0,%1,%2,%3};"
                 : "+f"(c[0]), "+f"(c[1]), "+f"(c[2]), "+f"(c[3])
                 : "r"(a[0]), "r"(a[1]), "r"(a[2]), "r"(a[3]), "r"(b0), "r"(b1));
}
__device__ __forceinline__ void cpasync16(uint32_t dst, const void* src) {
    asm volatile("cp.async.cg.shared.global [%0], [%1], 16;" :: "r"(dst), "l"(src));
}
template<int N> __device__ __forceinline__ void cpwait() {
    asm volatile("cp.async.wait_group %0;" :: "n"(N));
}
#define CP_COMMIT() asm volatile("cp.async.commit_group;" ::: "memory")

// ---------------- kernel 1: nodes -> fp16 hi/lo ----------------
__global__ void prep_nodes_kernel(const float* __restrict__ nodes) {
    int idx = blockIdx.x * blockDim.x + threadIdx.x;    // float4 index
    if (idx >= MTOT * DDIM / 4) return;
    float4 v = reinterpret_cast<const float4*>(nodes)[idx];
    __half h0 = __float2half_rn(v.x), h1 = __float2half_rn(v.y);
    __half h2 = __float2half_rn(v.z), h3 = __float2half_rn(v.w);
    __half l0 = __float2half_rn(v.x - __half2float(h0));
    __half l1 = __float2half_rn(v.y - __half2float(h1));
    __half l2 = __float2half_rn(v.z - __half2float(h2));
    __half l3 = __float2half_rn(v.w - __half2float(h3));
    __half2 hA = {h0, h1}, hB = {h2, h3}, lA = {l0, l1}, lB = {l2, l3};
    uint2 hp = make_uint2(*reinterpret_cast<uint32_t*>(&hA), *reinterpret_cast<uint32_t*>(&hB));
    uint2 lp = make_uint2(*reinterpret_cast<uint32_t*>(&lA), *reinterpret_cast<uint32_t*>(&lB));
    reinterpret_cast<uint2*>(g_nhi)[idx] = hp;
    reinterpret_cast<uint2*>(g_nlo)[idx] = lp;
}

// ---------------- kernel 2: weights -> fp16 + flag reset -----------------
__global__ void prep_w_kernel(const float* __restrict__ w0,
                              const float* __restrict__ wr) {
    int idx = blockIdx.x * blockDim.x + threadIdx.x;
    if (idx < NGROUPS) g_flag[idx] = 0;
    if (idx >= 6 * HDIM * DDIM) return;
    int g = idx / (HDIM * DDIM);
    int r = idx % (HDIM * DDIM);      // = h*DDIM + d
    float v = (g == 0) ? w0[r] : wr[(g - 1) * HDIM * DDIM + r];
    __half h = __float2half_rn(v);
    g_whi[idx] = h;
    if (g == 0) g_wlo[r] = __float2half_rn(v - __half2float(h));
}

// ---------------- kernel 3: heterogeneous rowsum + fused GEMM ------------
// 2304 blocks, 256 threads. Block bid: group mt = bid/9, role = bid%9.
//  role 0..4 : rowsum producer — relation `role` scales for m-tile mt
//              (128 adj rows), then threadfence + flag[mt]++.
//  role 5..8 : R9 GEMM tile (mt, role-5). Scale read happens at chunk c==2
//              after spinning on flag[mt]==5. Producers have lower block IDs
//              -> dispatched earlier (wave-1 LUT + ID-ordered work-steal)
//              -> always running/done before any consumer spins; producers
//              never wait -> guaranteed progress, no deadlock.
__global__ __launch_bounds__(256, 1) void fused_kernel(
        const float* __restrict__ adj, float* __restrict__ out) {
    const int bid  = blockIdx.x;
    const int mt   = bid / GROUP;
    const int role = bid - mt * GROUP;
    const int tid  = threadIdx.x;
    const int wid  = tid >> 5;
    const int lane = tid & 31;

    if (role < RDIM) {
        // ---- rowsum producer: 128 rows, warp per 16 rows, 2-row interleave
        const int b  = mt >> 3;
        const int n0 = (mt & 7) * 128;
        const size_t base = (size_t)(b * RDIM + role) * NNODES + n0 + wid * 16;
        #pragma unroll 1
        for (int r = 0; r < 16; r += 2) {
            size_t ridx = base + r;
            const float4* rp0 = reinterpret_cast<const float4*>(adj) + ridx * 256;
            const float4* rp1 = rp0 + 256;
            float s0 = 0.0f, s1 = 0.0f;
            #pragma unroll
            for (int i = 0; i < 8; i++) {
                float4 v0 = __ldcs(&rp0[lane + i * 32]);
                float4 v1 = __ldcs(&rp1[lane + i * 32]);
                s0 += (v0.x + v0.y) + (v0.z + v0.w);
                s1 += (v1.x + v1.y) + (v1.z + v1.w);
            }
            #pragma unroll
            for (int o = 16; o > 0; o >>= 1) {
                s0 += __shfl_xor_sync(0xffffffffu, s0, o);
                s1 += __shfl_xor_sync(0xffffffffu, s1, o);
            }
            if (lane == 0) {
                if (s0 == 0.0f) s0 = 1.0f;
                if (s1 == 0.0f) s1 = 1.0f;
                g_invc[ridx]     = 1.0f / s0;
                g_invc[ridx + 1] = 1.0f / s1;
            }
        }
        __syncthreads();
        if (tid == 0) {
            __threadfence();
            atomicAdd(&g_flag[mt], 1);
        }
        return;
    }

    // ================= GEMM role (R9 core, verbatim) =================
    extern __shared__ char smem[];
    const uint32_t sb = smem_u32(smem);
    const int wm = (wid >> 1);          // 0..3
    const int wh = wid & 1;             // 0..1
    const int tile_m = mt * TM;
    const int tile_h = (role - RDIM) * TH;

    // ---- async-stage A hi/lo: [TM x 256] fp16 (group 0) ----
    #pragma unroll
    for (int i = tid; i < TM * 32; i += 256) {
        int row = i >> 5;
        int cq  = i & 31;
        size_t src = (size_t)(tile_m + row) * DDIM + cq * 8;
        uint32_t d = sb + (uint32_t)row * SAB + cq * 16;
        cpasync16(d + SM_AHI, &g_nhi[src]);
        cpasync16(d + SM_ALO, &g_nlo[src]);
    }
    CP_COMMIT();

    // ---- chunk prefetch helper ----
    auto stage_chunk = [&](int stage, int c) {
        uint32_t base = sb + SM_B0 + (uint32_t)stage * BSTAGE;
        if (c < 2) {
            #pragma unroll
            for (int i = tid; i < TH * 16; i += 256) {
                int row = i >> 4;
                int cq  = i & 15;
                size_t src = (size_t)(tile_h + row) * DDIM + c * 128 + cq * 8;
                uint32_t d = base + (uint32_t)row * BROW + cq * 16;
                cpasync16(d, &g_whi[src]);
                cpasync16(d + BCHUNK, &g_wlo[src]);
            }
        } else {
            int g = c - 1;
            #pragma unroll
            for (int i = tid; i < TH * 32; i += 256) {
                int row = i >> 5;
                int cq  = i & 31;
                size_t src = ((size_t)g * HDIM + tile_h + row) * DDIM + cq * 8;
                uint32_t d = base + (uint32_t)row * BROWR + cq * 16;
                cpasync16(d, &g_whi[src]);
            }
        }
        CP_COMMIT();
    };

    stage_chunk(0, 0);      // group 1

    const uint32_t aRow = (uint32_t)(wm * 32 + (lane & 15)) * SAB + (lane >> 4) * 16;
    const uint32_t aHi0 = sb + SM_AHI + aRow;
    const uint32_t aHi1 = aHi0 + 16 * SAB;
    const uint32_t aLo0 = sb + SM_ALO + aRow;
    const uint32_t aLo1 = aLo0 + 16 * SAB;
    const int n_loc  = (lane & 7) + ((lane >> 4) << 3);
    const int k_half = (lane >> 3) & 1;
    const uint32_t bOffH = (uint32_t)(wh * 32 + n_loc) * BROW  + (uint32_t)k_half * 16;
    const uint32_t bOffR = (uint32_t)(wh * 32 + n_loc) * BROWR + (uint32_t)k_half * 16;

    const int r0 = tile_m + wm * 32 + (lane >> 2);
    float sc[RDIM][4];                  // loaded at c==2, after producers done

    float run[2][4][4];
    #pragma unroll
    for (int mi = 0; mi < 2; mi++)
        #pragma unroll
        for (int ni = 0; ni < 4; ni++)
            #pragma unroll
            for (int c = 0; c < 4; c++) run[mi][ni][c] = 0.0f;

    #pragma unroll 1
    for (int c = 0; c < NCHUNK; c++) {
        if (c + 1 < NCHUNK) {
            stage_chunk((c + 1) & 1, c + 1);
            cpwait<1>();
        } else {
            cpwait<0>();
        }

        if (c == 2) {
            // wait for this group's 5 rowsum producers, then load scales
            if (tid == 0) {
                while (((volatile int*)g_flag)[mt] != RDIM) __nanosleep(64);
                __threadfence();
            }
            __syncthreads();
            #pragma unroll
            for (int g = 0; g < RDIM; g++)
                #pragma unroll
                for (int j = 0; j < 4; j++) {
                    int row = r0 + j * 8;
                    int b = row >> 10, n = row & 1023;
                    sc[g][j] = __ldcg(&g_invc[((size_t)b * RDIM + g) * NNODES + n]);
                }
        }
        __syncthreads();

        const uint32_t stb = sb + SM_B0 + (uint32_t)(c & 1) * BSTAGE;

        if (c < 2) {
            // ---- w0 half-K chunk: 3-pass split, accumulate into run ----
            const uint32_t kaBase = (uint32_t)c * 256;
            const uint32_t bH = stb + bOffH;
            const uint32_t bL = stb + BCHUNK + bOffH;
            #pragma unroll 2
            for (int kc = 0; kc < 8; kc++) {
                const uint32_t ko = (uint32_t)kc * 32;
                const uint32_t ka = kaBase + ko;
                uint32_t ah0[4], ah1[4], al0[4], al1[4];
                uint32_t bh0[4], bh1[4], bl0[4], bl1[4];
                ldm4(ah0, aHi0 + ka);
                ldm4(ah1, aHi1 + ka);
                ldm4(bh0, bH + ko);
                ldm4(bh1, bH + 16 * BROW + ko);
                ldm4(al0, aLo0 + ka);
                ldm4(al1, aLo1 + ka);
                ldm4(bl0, bL + ko);
                ldm4(bl1, bL + 16 * BROW + ko);
                // hi*hi
                mma16816(run[0][0], ah0, bh0[0], bh0[1]);
                mma16816(run[0][1], ah0, bh0[2], bh0[3]);
                mma16816(run[0][2], ah0, bh1[0], bh1[1]);
                mma16816(run[0][3], ah0, bh1[2], bh1[3]);
                mma16816(run[1][0], ah1, bh0[0], bh0[1]);
                mma16816(run[1][1], ah1, bh0[2], bh0[3]);
                mma16816(run[1][2], ah1, bh1[0], bh1[1]);
                mma16816(run[1][3], ah1, bh1[2], bh1[3]);
                // hi*lo
                mma16816(run[0][0], ah0, bl0[0], bl0[1]);
                mma16816(run[0][1], ah0, bl0[2], bl0[3]);
                mma16816(run[0][2], ah0, bl1[0], bl1[1]);
                mma16816(run[0][3], ah0, bl1[2], bl1[3]);
                mma16816(run[1][0], ah1, bl0[0], bl0[1]);
                mma16816(run[1][1], ah1, bl0[2], bl0[3]);
                mma16816(run[1][2], ah1, bl1[0], bl1[1]);
                mma16816(run[1][3], ah1, bl1[2], bl1[3]);
                // lo*hi
                mma16816(run[0][0], al0, bh0[0], bh0[1]);
                mma16816(run[0][1], al0, bh0[2], bh0[3]);
                mma16816(run[0][2], al0, bh1[0], bh1[1]);
                mma16816(run[0][3], al0, bh1[2], bh1[3]);
                mma16816(run[1][0], al1, bh0[0], bh0[1]);
                mma16816(run[1][1], al1, bh0[2], bh0[3]);
                mma16816(run[1][2], al1, bh1[0], bh1[1]);
                mma16816(run[1][3], al1, bh1[2], bh1[3]);
            }
        } else {
            // ---- relation full-K chunk: 1-pass fp16 into acc ----
            float acc[2][4][4];
            #pragma unroll
            for (int mi = 0; mi < 2; mi++)
                #pragma unroll
                for (int ni = 0; ni < 4; ni++)
                    #pragma unroll
                    for (int q = 0; q < 4; q++) acc[mi][ni][q] = 0.0f;

            const uint32_t bH = stb + bOffR;
            #pragma unroll 4
            for (int kc = 0; kc < 16; kc++) {
                const uint32_t ko = (uint32_t)kc * 32;
                uint32_t a0[4], a1[4], b0[4], b1[4];
                ldm4(a0, aHi0 + ko);
                ldm4(a1, aHi1 + ko);
                ldm4(b0, bH + ko);
                ldm4(b1, bH + 16 * BROWR + ko);
                mma16816(acc[0][0], a0, b0[0], b0[1]);
                mma16816(acc[0][1], a0, b0[2], b0[3]);
                mma16816(acc[0][2], a0, b1[0], b1[1]);
                mma16816(acc[0][3], a0, b1[2], b1[3]);
                mma16816(acc[1][0], a1, b0[0], b0[1]);
                mma16816(acc[1][1], a1, b0[2], b0[3]);
                mma16816(acc[1][2], a1, b1[0], b1[1]);
                mma16816(acc[1][3], a1, b1[2], b1[3]);
            }

            const int g = c - 2;
            #pragma unroll
            for (int mi = 0; mi < 2; mi++)
                #pragma unroll
                for (int ni = 0; ni < 4; ni++) {
                    float s0 = sc[g][mi * 2 + 0];
                    float s1 = sc[g][mi * 2 + 1];
                    run[mi][ni][0] += s0 * acc[mi][ni][0];
                    run[mi][ni][1] += s0 * acc[mi][ni][1];
                    run[mi][ni][2] += s1 * acc[mi][ni][2];
                    run[mi][ni][3] += s1 * acc[mi][ni][3];
                }
        }
        __syncthreads();    // stage (c&1) reusable at c+1
    }

    // ---- epilogue: write fp32 output ----
    #pragma unroll
    for (int mi = 0; mi < 2; mi++) {
        int rowA = tile_m + wm * 32 + mi * 16 + (lane >> 2);
        #pragma unroll
        for (int ni = 0; ni < 4; ni++) {
            int col = tile_h + wh * 32 + ni * 8 + (lane & 3) * 2;
            *reinterpret_cast<float2*>(&out[(size_t)rowA * HDIM + col]) =
                make_float2(run[mi][ni][0], run[mi][ni][1]);
            *reinterpret_cast<float2*>(&out[(size_t)(rowA + 8) * HDIM + col]) =
                make_float2(run[mi][ni][2], run[mi][ni][3]);
        }
    }
}

// ---------------- launch ----------------
extern "C" void kernel_launch(void* const* d_in, const int* in_sizes, int n_in,
                              void* d_out, int out_size) {
    const float* nodes = (const float*)d_in[0];
    const float* adj   = (const float*)d_in[1];
    const float* w0    = (const float*)d_in[2];
    const float* wr    = (const float*)d_in[3];
    float* out = (float*)d_out;

    cudaFuncSetAttribute(fused_kernel,
                         cudaFuncAttributeMaxDynamicSharedMemorySize, SM_TOTAL);

    prep_nodes_kernel<<<(MTOT * DDIM / 4 + 255) / 256, 256>>>(nodes);
    prep_w_kernel<<<(6 * HDIM * DDIM + 255) / 256, 256>>>(w0, wr);
    fused_kernel<<<NBLOCKS, 256, SM_TOTAL>>>(adj, out);
}

// round 14
// speedup vs baseline: 1.4566x; 1.4566x over previous
#include <cuda_runtime.h>
#include <cuda_fp16.h>
#include <cstdint>

// ---------------- problem dims (fixed) ----------------
#define BATCH   32
#define RDIM    5
#define NNODES  1024
#define DDIM    256
#define HDIM    256
#define MTOT    (BATCH * NNODES)    // 32768

// ---------------- tiling (R9-proven GEMM core, A-lo pass removed) --------
#define TM      128                 // CTA M tile
#define TH      64                  // CTA H tile
#define SA      264                 // padded A row stride (fp16 elems), 528 B
#define SAB     (SA * 2)
#define ASZ     (TM * SAB)          // 67584 B (A hi only)

// w0 chunks: 64 rows x 128 cols fp16, row stride 272 B (hi at 0, lo at +BCHUNK)
#define BROW    272
#define BCHUNK  (TH * BROW)         // 17408
// relation chunks: 64 rows x 256 cols fp16, row stride 528 B
#define BROWR   528
#define BSTAGE  34816               // stage slot (fits both chunk types)
#define NCHUNK  7                   // c0,c1: w0 half-K (2-pass); c2..c6: rel full-K

#define SM_B0   ASZ                        // 67584
#define SM_TOTAL (SM_B0 + 2 * BSTAGE)      // 137216 B

// ---------------- device scratch ----------------
__device__ __align__(16) __half g_nhi[MTOT * DDIM];        // nodes fp16 hi [m][d]
__device__ __align__(16) __half g_whi[6 * HDIM * DDIM];    // [g][h][d] fp16 (g0=w0)
__device__ __align__(16) __half g_wlo[HDIM * DDIM];        // w0 fp16 lo
__device__ float g_invc[BATCH * RDIM * NNODES];            // 1/rowsum (0 -> 1)

// ---------------- helpers ----------------
__device__ __forceinline__ uint32_t smem_u32(const void* p) {
    uint32_t a;
    asm("{ .reg .u64 t; cvta.to.shared.u64 t, %1; cvt.u32.u64 %0, t; }" : "=r"(a) : "l"(p));
    return a;
}
__device__ __forceinline__ void ldm4(uint32_t* r, uint32_t addr) {
    asm volatile("ldmatrix.sync.aligned.m8n8.x4.shared.b16 {%0,%1,%2,%3}, [%4];"
                 : "=r"(r[0]), "=r"(r[1]), "=r"(r[2]), "=r"(r[3]) : "r"(addr));
}
__device__ __forceinline__ void mma16816(float* c, const uint32_t* a,
                                         uint32_t b0, uint32_t b1) {
    asm volatile("mma.sync.aligned.m16n8k16.row.col.f32.f16.f16.f32 "
                 "{%0,%1,%2,%3}, {%4,%5,%6,%7}, {%8,%9}, {%0,%1,%2,%3};"
                 : "+f"(c[0]), "+f"(c[1]), "+f"(c[2]), "+f"(c[3])
                 : "r"(a[0]), "r"(a[1]), "r"(a[2]), "r"(a[3]), "r"(b0), "r"(b1));
}
__device__ __forceinline__ void cpasync16(uint32_t dst, const void* src) {
    asm volatile("cp.async.cg.shared.global [%0], [%1], 16;" :: "r"(dst), "l"(src));
}
template<int N> __device__ __forceinline__ void cpwait() {
    asm volatile("cp.async.wait_group %0;" :: "n"(N));
}
#define CP_COMMIT() asm volatile("cp.async.commit_group;" ::: "memory")

// ---------------- kernel 1: adj row sums -> reciprocal ----------------
__global__ void row_sum_kernel(const float* __restrict__ adj) {
    int gwarp = (blockIdx.x * blockDim.x + threadIdx.x) >> 5;
    int lane  = threadIdx.x & 31;
    if (gwarp >= BATCH * RDIM * NNODES) return;
    const float4* row = reinterpret_cast<const float4*>(adj) + (size_t)gwarp * 256;
    float s = 0.0f;
    #pragma unroll
    for (int i = 0; i < 8; i++) {
        float4 v = row[lane + i * 32];
        s += (v.x + v.y) + (v.z + v.w);
    }
    #pragma unroll
    for (int o = 16; o > 0; o >>= 1) s += __shfl_xor_sync(0xffffffffu, s, o);
    if (lane == 0) {
        if (s == 0.0f) s = 1.0f;
        g_invc[gwarp] = 1.0f / s;
    }
}

// ---------------- kernel 2: nodes -> fp16 hi only ----------------
__global__ void prep_nodes_kernel(const float* __restrict__ nodes) {
    int idx = blockIdx.x * blockDim.x + threadIdx.x;    // float4 index
    if (idx >= MTOT * DDIM / 4) return;
    float4 v = reinterpret_cast<const float4*>(nodes)[idx];
    __half2 hA = {__float2half_rn(v.x), __float2half_rn(v.y)};
    __half2 hB = {__float2half_rn(v.z), __float2half_rn(v.w)};
    reinterpret_cast<uint2*>(g_nhi)[idx] =
        make_uint2(*reinterpret_cast<uint32_t*>(&hA), *reinterpret_cast<uint32_t*>(&hB));
}

// ---------------- kernel 3: weights -> stacked [g][h][d] fp16 ------------
__global__ void prep_w_kernel(const float* __restrict__ w0,
                              const float* __restrict__ wr) {
    int idx = blockIdx.x * blockDim.x + threadIdx.x;
    if (idx >= 6 * HDIM * DDIM) return;
    int g = idx / (HDIM * DDIM);
    int r = idx % (HDIM * DDIM);      // = h*DDIM + d
    float v = (g == 0) ? w0[r] : wr[(g - 1) * HDIM * DDIM + r];
    __half h = __float2half_rn(v);
    g_whi[idx] = h;
    if (g == 0) g_wlo[r] = __float2half_rn(v - __half2float(h));
}

// ---------------- kernel 4: mma.sync fp16 fused multi-GEMM ---------------
// grid (MTOT/TM, HDIM/TH), 256 threads (8 warps, 4x2 over (m,h)).
// c0,c1: w0 half-K chunks, 2-pass: A_hi x (B_hi + B_lo), accumulated in run.
// c2..c6: relation g=c-1 full-K chunk, 1-pass fp16; run += s(g,m)*acc.
// B chunks double-buffered via cp.async.
__global__ __launch_bounds__(256, 1) void gemm_mma_kernel(float* __restrict__ out) {
    extern __shared__ char smem[];
    const uint32_t sb = smem_u32(smem);
    const int tid  = threadIdx.x;
    const int wid  = tid >> 5;
    const int lane = tid & 31;
    const int wm = wid >> 1;            // 0..3
    const int wh = wid & 1;             // 0..1
    const int tile_m = blockIdx.x * TM;
    const int tile_h = blockIdx.y * TH;

    // ---- async-stage A hi: [TM x 256] fp16 (group 0) ----
    #pragma unroll
    for (int i = tid; i < TM * 32; i += 256) {
        int row = i >> 5;
        int cq  = i & 31;
        size_t src = (size_t)(tile_m + row) * DDIM + cq * 8;
        cpasync16(sb + (uint32_t)row * SAB + cq * 16, &g_nhi[src]);
    }
    CP_COMMIT();

    // ---- chunk prefetch helper ----
    auto stage_chunk = [&](int stage, int c) {
        uint32_t base = sb + SM_B0 + (uint32_t)stage * BSTAGE;
        if (c < 2) {
            // w0 half-K chunk: hi + lo, 64 rows x 128 cols
            #pragma unroll
            for (int i = tid; i < TH * 16; i += 256) {
                int row = i >> 4;
                int cq  = i & 15;
                size_t src = (size_t)(tile_h + row) * DDIM + c * 128 + cq * 8;
                uint32_t d = base + (uint32_t)row * BROW + cq * 16;
                cpasync16(d, &g_whi[src]);
                cpasync16(d + BCHUNK, &g_wlo[src]);
            }
        } else {
            // relation full-K chunk: hi only, 64 rows x 256 cols
            int g = c - 1;
            #pragma unroll
            for (int i = tid; i < TH * 32; i += 256) {
                int row = i >> 5;
                int cq  = i & 31;
                size_t src = ((size_t)g * HDIM + tile_h + row) * DDIM + cq * 8;
                cpasync16(base + (uint32_t)row * BROWR + cq * 16, &g_whi[src]);
            }
        }
        CP_COMMIT();
    };

    stage_chunk(0, 0);      // group 1

    // ---- per-thread ldmatrix base offsets ----
    const uint32_t aRow = (uint32_t)(wm * 32 + (lane & 15)) * SAB + (lane >> 4) * 16;
    const uint32_t aHi0 = sb + aRow;
    const uint32_t aHi1 = aHi0 + 16 * SAB;
    const int n_loc  = (lane & 7) + ((lane >> 4) << 3);
    const int k_half = (lane >> 3) & 1;
    const uint32_t bOffH = (uint32_t)(wh * 32 + n_loc) * BROW  + (uint32_t)k_half * 16;
    const uint32_t bOffR = (uint32_t)(wh * 32 + n_loc) * BROWR + (uint32_t)k_half * 16;

    // ---- per-row scales (4 rows per thread: +0,+8,+16,+24), relations ----
    const int r0 = tile_m + wm * 32 + (lane >> 2);
    float sc[RDIM][4];
    #pragma unroll
    for (int g = 0; g < RDIM; g++)
        #pragma unroll
        for (int j = 0; j < 4; j++) {
            int row = r0 + j * 8;
            int b = row >> 10, n = row & 1023;
            sc[g][j] = g_invc[((size_t)b * RDIM + g) * NNODES + n];
        }

    float run[2][4][4];
    #pragma unroll
    for (int mi = 0; mi < 2; mi++)
        #pragma unroll
        for (int ni = 0; ni < 4; ni++)
            #pragma unroll
            for (int c = 0; c < 4; c++) run[mi][ni][c] = 0.0f;

    #pragma unroll 1
    for (int c = 0; c < NCHUNK; c++) {
        if (c + 1 < NCHUNK) {
            stage_chunk((c + 1) & 1, c + 1);
            cpwait<1>();        // chunk c (and A) arrived; c+1 in flight
        } else {
            cpwait<0>();
        }
        __syncthreads();

        const uint32_t stb = sb + SM_B0 + (uint32_t)(c & 1) * BSTAGE;

        if (c < 2) {
            // ---- w0 half-K chunk: 2-pass (B-side split), accumulate in run
            const uint32_t kaBase = (uint32_t)c * 256;      // c*8*32
            const uint32_t bH = stb + bOffH;
            const uint32_t bL = stb + BCHUNK + bOffH;
            #pragma unroll 2
            for (int kc = 0; kc < 8; kc++) {
                const uint32_t ko = (uint32_t)kc * 32;
                const uint32_t ka = kaBase + ko;
                uint32_t ah0[4], ah1[4];
                uint32_t bh0[4], bh1[4], bl0[4], bl1[4];
                ldm4(ah0, aHi0 + ka);
                ldm4(ah1, aHi1 + ka);
                ldm4(bh0, bH + ko);
                ldm4(bh1, bH + 16 * BROW + ko);
                ldm4(bl0, bL + ko);
                ldm4(bl1, bL + 16 * BROW + ko);

                // hi * hi
                mma16816(run[0][0], ah0, bh0[0], bh0[1]);
                mma16816(run[0][1], ah0, bh0[2], bh0[3]);
                mma16816(run[0][2], ah0, bh1[0], bh1[1]);
                mma16816(run[0][3], ah0, bh1[2], bh1[3]);
                mma16816(run[1][0], ah1, bh0[0], bh0[1]);
                mma16816(run[1][1], ah1, bh0[2], bh0[3]);
                mma16816(run[1][2], ah1, bh1[0], bh1[1]);
                mma16816(run[1][3], ah1, bh1[2], bh1[3]);
                // hi * lo
                mma16816(run[0][0], ah0, bl0[0], bl0[1]);
                mma16816(run[0][1], ah0, bl0[2], bl0[3]);
                mma16816(run[0][2], ah0, bl1[0], bl1[1]);
                mma16816(run[0][3], ah0, bl1[2], bl1[3]);
                mma16816(run[1][0], ah1, bl0[0], bl0[1]);
                mma16816(run[1][1], ah1, bl0[2], bl0[3]);
                mma16816(run[1][2], ah1, bl1[0], bl1[1]);
                mma16816(run[1][3], ah1, bl1[2], bl1[3]);
            }
        } else {
            // ---- relation full-K chunk: 1-pass fp16 into acc ----
            float acc[2][4][4];
            #pragma unroll
            for (int mi = 0; mi < 2; mi++)
                #pragma unroll
                for (int ni = 0; ni < 4; ni++)
                    #pragma unroll
                    for (int q = 0; q < 4; q++) acc[mi][ni][q] = 0.0f;

            const uint32_t bH = stb + bOffR;
            #pragma unroll 4
            for (int kc = 0; kc < 16; kc++) {
                const uint32_t ko = (uint32_t)kc * 32;
                uint32_t a0[4], a1[4], b0[4], b1[4];
                ldm4(a0, aHi0 + ko);
                ldm4(a1, aHi1 + ko);
                ldm4(b0, bH + ko);
                ldm4(b1, bH + 16 * BROWR + ko);
                mma16816(acc[0][0], a0, b0[0], b0[1]);
                mma16816(acc[0][1], a0, b0[2], b0[3]);
                mma16816(acc[0][2], a0, b1[0], b1[1]);
                mma16816(acc[0][3], a0, b1[2], b1[3]);
                mma16816(acc[1][0], a1, b0[0], b0[1]);
                mma16816(acc[1][1], a1, b0[2], b0[3]);
                mma16816(acc[1][2], a1, b1[0], b1[1]);
                mma16816(acc[1][3], a1, b1[2], b1[3]);
            }

            const int g = c - 2;            // 0..4 -> relation index
            #pragma unroll
            for (int mi = 0; mi < 2; mi++)
                #pragma unroll
                for (int ni = 0; ni < 4; ni++) {
                    float s0 = sc[g][mi * 2 + 0];
                    float s1 = sc[g][mi * 2 + 1];
                    run[mi][ni][0] += s0 * acc[mi][ni][0];
                    run[mi][ni][1] += s0 * acc[mi][ni][1];
                    run[mi][ni][2] += s1 * acc[mi][ni][2];
                    run[mi][ni][3] += s1 * acc[mi][ni][3];
                }
        }
        __syncthreads();    // stage (c&1) free for reuse at iteration c+1
    }

    // ---- epilogue: write fp32 output ----
    #pragma unroll
    for (int mi = 0; mi < 2; mi++) {
        int rowA = tile_m + wm * 32 + mi * 16 + (lane >> 2);
        #pragma unroll
        for (int ni = 0; ni < 4; ni++) {
            int col = tile_h + wh * 32 + ni * 8 + (lane & 3) * 2;
            *reinterpret_cast<float2*>(&out[(size_t)rowA * HDIM + col]) =
                make_float2(run[mi][ni][0], run[mi][ni][1]);
            *reinterpret_cast<float2*>(&out[(size_t)(rowA + 8) * HDIM + col]) =
                make_float2(run[mi][ni][2], run[mi][ni][3]);
        }
    }
}

// ---------------- launch ----------------
extern "C" void kernel_launch(void* const* d_in, const int* in_sizes, int n_in,
                              void* d_out, int out_size) {
    const float* nodes = (const float*)d_in[0];
    const float* adj   = (const float*)d_in[1];
    const float* w0    = (const float*)d_in[2];
    const float* wr    = (const float*)d_in[3];
    float* out = (float*)d_out;

    cudaFuncSetAttribute(gemm_mma_kernel,
                         cudaFuncAttributeMaxDynamicSharedMemorySize, SM_TOTAL);

    {
        int nthreads = BATCH * RDIM * NNODES * 32;
        row_sum_kernel<<<(nthreads + 255) / 256, 256>>>(adj);
    }
    prep_nodes_kernel<<<(MTOT * DDIM / 4 + 255) / 256, 256>>>(nodes);
    prep_w_kernel<<<(6 * HDIM * DDIM + 255) / 256, 256>>>(w0, wr);
    gemm_mma_kernel<<<dim3(MTOT / TM, HDIM / TH), 256, SM_TOTAL>>>(out);
}

// round 16
// speedup vs baseline: 1.6321x; 1.1204x over previous
#include <cuda_runtime.h>
#include <cuda_fp16.h>
#include <cstdint>

// ---------------- problem dims (fixed) ----------------
#define BATCH   32
#define RDIM    5
#define NNODES  1024
#define DDIM    256
#define HDIM    256
#define MTOT    (BATCH * NNODES)    // 32768

// ---------------- tiling (R9-proven GEMM core, pure-fp16 everywhere) -----
#define TM      128                 // CTA M tile
#define TH      64                  // CTA H tile
#define SA      264                 // padded A row stride (fp16 elems), 528 B
#define SAB     (SA * 2)
#define ASZ     (TM * SAB)          // 67584 B (A hi only)

// chunk: 64 h-rows x 256 K fp16, row stride 528 B (hi only)
#define BROWR   528
#define BSTAGE  (TH * BROWR)        // 33792
#define NCHUNK  6                   // c0: w0 (scale 1); c1..c5: relations

#define SM_B0   ASZ                        // 67584
#define SM_TOTAL (SM_B0 + 2 * BSTAGE)      // 135168 B

// combined pre-kernel grid layout
#define NB_PN   8192                // prep_nodes blocks (float4 grid)
#define NB_PW   1536                // prep_w blocks
#define NB_RS   20480               // rowsum blocks (8 warps x 1 row each)
#define NB_PRE  (NB_PN + NB_PW + NB_RS)

// ---------------- device scratch ----------------
__device__ __align__(16) __half g_nhi[MTOT * DDIM];        // nodes fp16 [m][d]
__device__ __align__(16) __half g_whi[6 * HDIM * DDIM];    // [g][h][d] fp16 (g0=w0)
__device__ float g_invc[BATCH * RDIM * NNODES];            // 1/rowsum (0 -> 1)

// ---------------- helpers ----------------
__device__ __forceinline__ uint32_t smem_u32(const void* p) {
    uint32_t a;
    asm("{ .reg .u64 t; cvta.to.shared.u64 t, %1; cvt.u32.u64 %0, t; }" : "=r"(a) : "l"(p));
    return a;
}
__device__ __forceinline__ void ldm4(uint32_t* r, uint32_t addr) {
    asm volatile("ldmatrix.sync.aligned.m8n8.x4.shared.b16 {%0,%1,%2,%3}, [%4];"
                 : "=r"(r[0]), "=r"(r[1]), "=r"(r[2]), "=r"(r[3]) : "r"(addr));
}
__device__ __forceinline__ void mma16816(float* c, const uint32_t* a,
                                         uint32_t b0, uint32_t b1) {
    asm volatile("mma.sync.aligned.m16n8k16.row.col.f32.f16.f16.f32 "
                 "{%0,%1,%2,%3}, {%4,%5,%6,%7}, {%8,%9}, {%0,%1,%2,%3};"
                 : "+f"(c[0]), "+f"(c[1]), "+f"(c[2]), "+f"(c[3])
                 : "r"(a[0]), "r"(a[1]), "r"(a[2]), "r"(a[3]), "r"(b0), "r"(b1));
}
__device__ __forceinline__ void cpasync16(uint32_t dst, const void* src) {
    asm volatile("cp.async.cg.shared.global [%0], [%1], 16;" :: "r"(dst), "l"(src));
}
template<int N> __device__ __forceinline__ void cpwait() {
    asm volatile("cp.async.wait_group %0;" :: "n"(N));
}
#define CP_COMMIT() asm volatile("cp.async.commit_group;" ::: "memory")

// ---------------- kernel 1: combined prep (nodes, weights) + adj rowsum --
// 30208 blocks x 256 threads, role by blockIdx (all roles independent):
//  [0, 8192)        : nodes -> fp16, one float4 per thread
//  [8192, 9728)     : weights -> stacked fp16 [g][h][d]
//  [9728, 30208)    : adj row sums -> 1/rowsum; one warp per 1024-f row
__global__ void pre_kernel(const float* __restrict__ nodes,
                           const float* __restrict__ w0,
                           const float* __restrict__ wr,
                           const float* __restrict__ adj) {
    const int bid = blockIdx.x;
    const int tid = threadIdx.x;

    if (bid < NB_PN) {
        int idx = bid * 256 + tid;              // float4 index
        float4 v = reinterpret_cast<const float4*>(nodes)[idx];
        __half2 hA = {__float2half_rn(v.x), __float2half_rn(v.y)};
        __half2 hB = {__float2half_rn(v.z), __float2half_rn(v.w)};
        reinterpret_cast<uint2*>(g_nhi)[idx] =
            make_uint2(*reinterpret_cast<uint32_t*>(&hA),
                       *reinterpret_cast<uint32_t*>(&hB));
        return;
    }
    if (bid < NB_PN + NB_PW) {
        int idx = (bid - NB_PN) * 256 + tid;    // element index, 393216 total
        int g = idx / (HDIM * DDIM);
        int r = idx % (HDIM * DDIM);            // = h*DDIM + d
        float v = (g == 0) ? w0[r] : wr[(g - 1) * HDIM * DDIM + r];
        g_whi[idx] = __float2half_rn(v);
        return;
    }
    // rowsum role: one warp per adjacency row
    const int wid  = tid >> 5;
    const int lane = tid & 31;
    const size_t ridx = (size_t)(bid - NB_PN - NB_PW) * 8 + wid;
    const float4* row = reinterpret_cast<const float4*>(adj) + ridx * 256;
    float s = 0.0f;
    #pragma unroll
    for (int i = 0; i < 8; i++) {
        float4 v = __ldcs(&row[lane + i * 32]);
        s += (v.x + v.y) + (v.z + v.w);
    }
    #pragma unroll
    for (int o = 16; o > 0; o >>= 1) s += __shfl_xor_sync(0xffffffffu, s, o);
    if (lane == 0) {
        if (s == 0.0f) s = 1.0f;
        g_invc[ridx] = 1.0f / s;
    }
}

// ---------------- kernel 2: mma.sync fp16 fused multi-GEMM ---------------
// grid (MTOT/TM, HDIM/TH), 256 threads (8 warps, 4x2 over (m,h)).
// 6 uniform full-K chunks (g=0: w0 with scale 1; g=1..5: relations with
// s(g,m)); per chunk: acc = A x B_g^T over K=256, run += s*acc.
// B chunks double-buffered via cp.async.
__global__ __launch_bounds__(256, 1) void gemm_mma_kernel(float* __restrict__ out) {
    extern __shared__ char smem[];
    const uint32_t sb = smem_u32(smem);
    const int tid  = threadIdx.x;
    const int wid  = tid >> 5;
    const int lane = tid & 31;
    const int wm = wid >> 1;            // 0..3
    const int wh = wid & 1;             // 0..1
    const int tile_m = blockIdx.x * TM;
    const int tile_h = blockIdx.y * TH;

    // ---- async-stage A: [TM x 256] fp16 (group 0) ----
    #pragma unroll
    for (int i = tid; i < TM * 32; i += 256) {
        int row = i >> 5;
        int cq  = i & 31;
        size_t src = (size_t)(tile_m + row) * DDIM + cq * 8;
        cpasync16(sb + (uint32_t)row * SAB + cq * 16, &g_nhi[src]);
    }
    CP_COMMIT();

    // ---- chunk prefetch: B_g full-K tile ----
    auto stage_chunk = [&](int stage, int g) {
        uint32_t base = sb + SM_B0 + (uint32_t)stage * BSTAGE;
        #pragma unroll
        for (int i = tid; i < TH * 32; i += 256) {
            int row = i >> 5;
            int cq  = i & 31;
            size_t src = ((size_t)g * HDIM + tile_h + row) * DDIM + cq * 8;
            cpasync16(base + (uint32_t)row * BROWR + cq * 16, &g_whi[src]);
        }
        CP_COMMIT();
    };

    stage_chunk(0, 0);      // group 1

    // ---- per-thread ldmatrix base offsets ----
    const uint32_t aRow = (uint32_t)(wm * 32 + (lane & 15)) * SAB + (lane >> 4) * 16;
    const uint32_t aHi0 = sb + aRow;
    const uint32_t aHi1 = aHi0 + 16 * SAB;
    const int n_loc  = (lane & 7) + ((lane >> 4) << 3);
    const int k_half = (lane >> 3) & 1;
    const uint32_t bOffR = (uint32_t)(wh * 32 + n_loc) * BROWR + (uint32_t)k_half * 16;

    // ---- per-row scales (4 rows per thread): g=0 -> 1, g>=1 -> invc -----
    const int r0 = tile_m + wm * 32 + (lane >> 2);
    float sc[NCHUNK][4];
    #pragma unroll
    for (int j = 0; j < 4; j++) sc[0][j] = 1.0f;
    #pragma unroll
    for (int g = 1; g < NCHUNK; g++)
        #pragma unroll
        for (int j = 0; j < 4; j++) {
            int row = r0 + j * 8;
            int b = row >> 10, n = row & 1023;
            sc[g][j] = g_invc[((size_t)b * RDIM + (g - 1)) * NNODES + n];
        }

    float run[2][4][4];
    #pragma unroll
    for (int mi = 0; mi < 2; mi++)
        #pragma unroll
        for (int ni = 0; ni < 4; ni++)
            #pragma unroll
            for (int q = 0; q < 4; q++) run[mi][ni][q] = 0.0f;

    #pragma unroll 1
    for (int c = 0; c < NCHUNK; c++) {
        if (c + 1 < NCHUNK) {
            stage_chunk((c + 1) & 1, c + 1);
            cpwait<1>();        // chunk c (and A) arrived; c+1 in flight
        } else {
            cpwait<0>();
        }
        __syncthreads();

        float acc[2][4][4];
        #pragma unroll
        for (int mi = 0; mi < 2; mi++)
            #pragma unroll
            for (int ni = 0; ni < 4; ni++)
                #pragma unroll
                for (int q = 0; q < 4; q++) acc[mi][ni][q] = 0.0f;

        const uint32_t bH = sb + SM_B0 + (uint32_t)(c & 1) * BSTAGE + bOffR;
        #pragma unroll 4
        for (int kc = 0; kc < 16; kc++) {
            const uint32_t ko = (uint32_t)kc * 32;
            uint32_t a0[4], a1[4], b0[4], b1[4];
            ldm4(a0, aHi0 + ko);
            ldm4(a1, aHi1 + ko);
            ldm4(b0, bH + ko);
            ldm4(b1, bH + 16 * BROWR + ko);
            mma16816(acc[0][0], a0, b0[0], b0[1]);
            mma16816(acc[0][1], a0, b0[2], b0[3]);
            mma16816(acc[0][2], a0, b1[0], b1[1]);
            mma16816(acc[0][3], a0, b1[2], b1[3]);
            mma16816(acc[1][0], a1, b0[0], b0[1]);
            mma16816(acc[1][1], a1, b0[2], b0[3]);
            mma16816(acc[1][2], a1, b1[0], b1[1]);
            mma16816(acc[1][3], a1, b1[2], b1[3]);
        }

        #pragma unroll
        for (int mi = 0; mi < 2; mi++)
            #pragma unroll
            for (int ni = 0; ni < 4; ni++) {
                float s0 = sc[c][mi * 2 + 0];
                float s1 = sc[c][mi * 2 + 1];
                run[mi][ni][0] += s0 * acc[mi][ni][0];
                run[mi][ni][1] += s0 * acc[mi][ni][1];
                run[mi][ni][2] += s1 * acc[mi][ni][2];
                run[mi][ni][3] += s1 * acc[mi][ni][3];
            }
        __syncthreads();    // stage (c&1) free for reuse at iteration c+1
    }

    // ---- epilogue: write fp32 output ----
    #pragma unroll
    for (int mi = 0; mi < 2; mi++) {
        int rowA = tile_m + wm * 32 + mi * 16 + (lane >> 2);
        #pragma unroll
        for (int ni = 0; ni < 4; ni++) {
            int col = tile_h + wh * 32 + ni * 8 + (lane & 3) * 2;
            *reinterpret_cast<float2*>(&out[(size_t)rowA * HDIM + col]) =
                make_float2(run[mi][ni][0], run[mi][ni][1]);
            *reinterpret_cast<float2*>(&out[(size_t)(rowA + 8) * HDIM + col]) =
                make_float2(run[mi][ni][2], run[mi][ni][3]);
        }
    }
}

// ---------------- launch ----------------
extern "C" void kernel_launch(void* const* d_in, const int* in_sizes, int n_in,
                              void* d_out, int out_size) {
    const float* nodes = (const float*)d_in[0];
    const float* adj   = (const float*)d_in[1];
    const float* w0    = (const float*)d_in[2];
    const float* wr    = (const float*)d_in[3];
    float* out = (float*)d_out;

    cudaFuncSetAttribute(gemm_mma_kernel,
                         cudaFuncAttributeMaxDynamicSharedMemorySize, SM_TOTAL);

    pre_kernel<<<NB_PRE, 256>>>(nodes, w0, wr, adj);
    gemm_mma_kernel<<<dim3(MTOT / TM, HDIM / TH), 256, SM_TOTAL>>>(out);
}